// round 16
// baseline (speedup 1.0000x reference)
#include <cuda_runtime.h>
#include <math.h>
#include <stdint.h>

#define LQ 2048
#define DM 256
#define NH 4
#define HDIM 64
#define NLAYER 6
#define MMEM 8192
#define VOCAB 50257
#define DFF 1024
#define NCHMAX 8

// ---------------- scratch ----------------
__device__ float g_x[LQ * DM];
__device__ float g_xn[LQ * DM];
__device__ float g_qkv[LQ * 3 * DM];
__device__ float g_o[LQ * DM];
__device__ float g_h1[LQ * DFF];
__device__ float g_res[(size_t)LQ * MMEM];   // scores; softmax converts in-place to tf32 u32
__device__ float g_ret[LQ * DM];
__device__ float g_xout[LQ * DM];
__device__ float g_split[4 * LQ * 768];      // split-K partials (24 MB)
__device__ float g_need[LQ];
__device__ float g_sal[LQ];
__device__ float g_gate[LQ];
// fast-tier pre-converted tf32 (u32)
__device__ uint32_t g_embu[VOCAB * DM];
__device__ uint32_t g_qnu[LQ * DM];
__device__ uint32_t g_knu[MMEM * DM];
__device__ uint32_t g_mvu[MMEM * DM];
__device__ uint32_t g_xoutu[LQ * DM];
// flash-attention partials: [NH][NCHMAX][LQ][HDIM]
__device__ float g_pacc[NH * NCHMAX * LQ * HDIM];
__device__ float g_pm[NH * NCHMAX * LQ];
__device__ float g_pl[NH * NCHMAX * LQ];

__device__ __forceinline__ uint32_t f2tf32(float f) {
    uint32_t u;
    asm("cvt.rna.tf32.f32 %0, %1;" : "=r"(u) : "f"(f));
    return u;
}
__device__ __forceinline__ void tf32_split(float f, uint32_t& b, uint32_t& s) {
    b = f2tf32(f);
    s = f2tf32(f - __uint_as_float(b));
}
__device__ __forceinline__ void cp16(void* dst, const void* src, bool ok) {
    uint32_t sa = (uint32_t)__cvta_generic_to_shared(dst);
    int sz = ok ? 16 : 0;
    asm volatile("cp.async.ca.shared.global [%0], [%1], 16, %2;\n"
                 :: "r"(sa), "l"(src), "r"(sz));
}

#define MMA(c, A0, A1, A2, A3, B0, B1)                                        \
    asm volatile("mma.sync.aligned.m16n8k8.row.col.f32.tf32.tf32.f32 "        \
                 "{%0,%1,%2,%3}, {%4,%5,%6,%7}, {%8,%9}, {%0,%1,%2,%3};\n"    \
                 : "+f"(c[0]), "+f"(c[1]), "+f"(c[2]), "+f"(c[3])             \
                 : "r"(A0), "r"(A1), "r"(A2), "r"(A3), "r"(B0), "r"(B1))

// ---------------- elementwise float -> tf32 u32 ----------------
__global__ void k_fcvt(const float* __restrict__ in, uint32_t* __restrict__ ou, int n) {
    int i = blockIdx.x * 256 + threadIdx.x;
    if (i < n) ou[i] = f2tf32(in[i]);
}

// ---------------- embedding lookup ----------------
__global__ void k_embed(const int* __restrict__ tokens, const float* __restrict__ embed,
                        float* __restrict__ x) {
    int idx = blockIdx.x * 256 + threadIdx.x;
    int l = idx >> 8, d = idx & 255;
    x[idx] = embed[(size_t)tokens[l] * DM + d];
}

// ---------------- rmsnorm (standalone; once before the loop) ----------------
__global__ void k_rmsnorm(const float* __restrict__ x, const float* __restrict__ w,
                          float* __restrict__ xn) {
    int l = blockIdx.x, t = threadIdx.x;
    __shared__ float red[256];
    float v = x[l * DM + t];
    red[t] = v * v;
    __syncthreads();
    for (int s = 128; s > 0; s >>= 1) {
        if (t < s) red[t] += red[t + s];
        __syncthreads();
    }
    float r = rsqrtf(red[0] / (float)DM + 1e-6f);
    xn[l * DM + t] = v * r * w[t];
}

// ---------------- accurate tf32x3 GEMM: 64x64 CTA tile, 128 thr, 5 CTAs/SM ----
#define ASTR2 20
#define ATILE (64 * ASTR2)
#define STG2 (2 * ATILE)
#define GEMM_SMEM2 (2 * STG2 * 4)       // 20480 B
__global__ void __launch_bounds__(128, 5)
k_gemm(const float* __restrict__ A, const float* __restrict__ B,
       float* __restrict__ P, int Mm, int Nn, int Kk, int kseg) {
    extern __shared__ float smem[];
    const int n0 = blockIdx.x * 64, m0 = blockIdx.y * 64;
    const int tid = threadIdx.x;
    const int w = tid >> 5, lane = tid & 31;
    const int g = lane >> 2, l4 = lane & 3;
    const int warp_m = (w >> 1) * 32;
    const int warp_n = (w & 1) * 32;
    const int kbeg = blockIdx.z * kseg;
    const int kend = kbeg + kseg;

    float acc[2][4][4];
#pragma unroll
    for (int i = 0; i < 2; i++)
#pragma unroll
        for (int j = 0; j < 4; j++)
#pragma unroll
            for (int r = 0; r < 4; r++) acc[i][j][r] = 0.f;

    const int row = tid >> 1, col8 = (tid & 1) * 8;

    auto load_tiles = [&](int k0, int st) {
        float* As = smem + st * STG2;
        float* Bs = As + ATILE;
        const float* sa = A + (size_t)(m0 + row) * Kk + k0 + col8;
        float* da = As + row * ASTR2 + col8;
        cp16(da, sa, true);
        cp16(da + 4, sa + 4, true);
        const float* sb = B + (size_t)(n0 + row) * Kk + k0 + col8;
        float* db = Bs + row * ASTR2 + col8;
        cp16(db, sb, true);
        cp16(db + 4, sb + 4, true);
        asm volatile("cp.async.commit_group;\n");
    };

    load_tiles(kbeg, 0);
    int stage = 0;
    for (int k0 = kbeg; k0 < kend; k0 += 16) {
        bool more = (k0 + 16) < kend;
        if (more) {
            load_tiles(k0 + 16, stage ^ 1);
            asm volatile("cp.async.wait_group 1;\n");
        } else {
            asm volatile("cp.async.wait_group 0;\n");
        }
        __syncthreads();

        const float* Af = smem + stage * STG2;
        const float* Bf = Af + ATILE;
#pragma unroll
        for (int ks = 0; ks < 2; ks++) {
            const int kc = ks * 8;
            uint32_t ab[2][4], ax[2][4], bb[4][2], bx[4][2];
#pragma unroll
            for (int mt = 0; mt < 2; mt++) {
                int r = (warp_m + mt * 16 + g) * ASTR2 + kc + l4;
                tf32_split(Af[r],                 ab[mt][0], ax[mt][0]);
                tf32_split(Af[r + 8 * ASTR2],     ab[mt][1], ax[mt][1]);
                tf32_split(Af[r + 4],             ab[mt][2], ax[mt][2]);
                tf32_split(Af[r + 8 * ASTR2 + 4], ab[mt][3], ax[mt][3]);
            }
#pragma unroll
            for (int nt = 0; nt < 4; nt++) {
                int r = (warp_n + nt * 8 + g) * ASTR2 + kc + l4;
                tf32_split(Bf[r],     bb[nt][0], bx[nt][0]);
                tf32_split(Bf[r + 4], bb[nt][1], bx[nt][1]);
            }
#pragma unroll
            for (int mt = 0; mt < 2; mt++)
#pragma unroll
                for (int nt = 0; nt < 4; nt++)
                    MMA(acc[mt][nt], ab[mt][0], ab[mt][1], ab[mt][2], ab[mt][3],
                        bb[nt][0], bb[nt][1]);
#pragma unroll
            for (int mt = 0; mt < 2; mt++)
#pragma unroll
                for (int nt = 0; nt < 4; nt++)
                    MMA(acc[mt][nt], ab[mt][0], ab[mt][1], ab[mt][2], ab[mt][3],
                        bx[nt][0], bx[nt][1]);
#pragma unroll
            for (int mt = 0; mt < 2; mt++)
#pragma unroll
                for (int nt = 0; nt < 4; nt++)
                    MMA(acc[mt][nt], ax[mt][0], ax[mt][1], ax[mt][2], ax[mt][3],
                        bb[nt][0], bb[nt][1]);
        }
        __syncthreads();
        stage ^= 1;
    }

    float* Pw = P + (size_t)blockIdx.z * Mm * Nn;
#pragma unroll
    for (int mt = 0; mt < 2; mt++)
#pragma unroll
        for (int nt = 0; nt < 4; nt++)
#pragma unroll
            for (int half = 0; half < 2; half++) {
                int m = m0 + warp_m + mt * 16 + g + half * 8;
#pragma unroll
                for (int cc = 0; cc < 2; cc++) {
                    int n = n0 + warp_n + nt * 8 + l4 * 2 + cc;
                    if (n < Nn)
                        Pw[(size_t)m * Nn + n] = acc[mt][nt][half * 2 + cc];
                }
            }
}

// ---------------- fast 1x tf32 GEMM: 64x64 tile, 128 thr, 5 CTAs/SM ----------------
// b_nt=1: B is [N,K]; b_nt=0: B is [K,N] (N multiple of 64).
#define BSTR3 68   // b_nt=0 transpose tile row stride (16 rows x 64 cols padded)
__global__ void __launch_bounds__(128, 5)
k_gemmp(const uint32_t* __restrict__ A, const uint32_t* __restrict__ B,
        float* __restrict__ C, int Mm, int Nn, int Kk, int b_nt, int kseg) {
    extern __shared__ uint32_t smu[];
    const int n0 = blockIdx.x * 64, m0 = blockIdx.y * 64;
    const int tid = threadIdx.x;
    const int w = tid >> 5, lane = tid & 31;
    const int g = lane >> 2, l4 = lane & 3;
    const int warp_m = (w >> 1) * 32;
    const int warp_n = (w & 1) * 32;
    const int kbeg = blockIdx.z * kseg;
    const int kend = kbeg + kseg;

    float acc[2][4][4];
#pragma unroll
    for (int i = 0; i < 2; i++)
#pragma unroll
        for (int j = 0; j < 4; j++)
#pragma unroll
            for (int r = 0; r < 4; r++) acc[i][j][r] = 0.f;

    const int row = tid >> 1, col8 = (tid & 1) * 8;

    auto load_tiles = [&](int k0, int st) {
        uint32_t* As = smu + st * STG2;
        uint32_t* Bs = As + ATILE;
        const uint32_t* sa = A + (size_t)(m0 + row) * Kk + k0 + col8;
        uint32_t* da = As + row * ASTR2 + col8;
        cp16(da, sa, true);
        cp16(da + 4, sa + 4, true);
        if (b_nt) {
            int gn = n0 + row;
            bool ok = gn < Nn;
            const uint32_t* sb = B + (size_t)(ok ? gn : 0) * Kk + k0 + col8;
            uint32_t* db = Bs + row * ASTR2 + col8;
            cp16(db, sb, ok);
            cp16(db + 4, sb + 4, ok);
        } else {   // B[K,N]: 16 rows x 64 cols; 8 threads/row, 8 u32 each
            int k = tid >> 3, colb = (tid & 7) * 8;
            const uint32_t* sb = B + (size_t)(k0 + k) * Nn + n0 + colb;
            uint32_t* db = Bs + k * BSTR3 + colb;
            cp16(db, sb, true);
            cp16(db + 4, sb + 4, true);
        }
        asm volatile("cp.async.commit_group;\n");
    };

    load_tiles(kbeg, 0);
    int stage = 0;
    for (int k0 = kbeg; k0 < kend; k0 += 16) {
        bool more = (k0 + 16) < kend;
        if (more) {
            load_tiles(k0 + 16, stage ^ 1);
            asm volatile("cp.async.wait_group 1;\n");
        } else {
            asm volatile("cp.async.wait_group 0;\n");
        }
        __syncthreads();

        const uint32_t* Af = smu + stage * STG2;
        const uint32_t* Bf = Af + ATILE;
#pragma unroll
        for (int ks = 0; ks < 2; ks++) {
            const int kc = ks * 8;
            uint32_t ab[2][4], bb[4][2];
#pragma unroll
            for (int mt = 0; mt < 2; mt++) {
                int r = (warp_m + mt * 16 + g) * ASTR2 + kc + l4;
                ab[mt][0] = Af[r];
                ab[mt][1] = Af[r + 8 * ASTR2];
                ab[mt][2] = Af[r + 4];
                ab[mt][3] = Af[r + 8 * ASTR2 + 4];
            }
            if (b_nt) {
#pragma unroll
                for (int nt = 0; nt < 4; nt++) {
                    int r = (warp_n + nt * 8 + g) * ASTR2 + kc + l4;
                    bb[nt][0] = Bf[r];
                    bb[nt][1] = Bf[r + 4];
                }
            } else {
#pragma unroll
                for (int nt = 0; nt < 4; nt++) {
                    int cn = warp_n + nt * 8 + g;
                    bb[nt][0] = Bf[(kc + l4) * BSTR3 + cn];
                    bb[nt][1] = Bf[(kc + l4 + 4) * BSTR3 + cn];
                }
            }
#pragma unroll
            for (int mt = 0; mt < 2; mt++)
#pragma unroll
                for (int nt = 0; nt < 4; nt++)
                    MMA(acc[mt][nt], ab[mt][0], ab[mt][1], ab[mt][2], ab[mt][3],
                        bb[nt][0], bb[nt][1]);
        }
        __syncthreads();
        stage ^= 1;
    }

    bool partial = (gridDim.z > 1);
    float* Cw = partial ? C + (size_t)blockIdx.z * Mm * Nn : C;
#pragma unroll
    for (int mt = 0; mt < 2; mt++)
#pragma unroll
        for (int nt = 0; nt < 4; nt++)
#pragma unroll
            for (int half = 0; half < 2; half++) {
                int m = m0 + warp_m + mt * 16 + g + half * 8;
#pragma unroll
                for (int cc = 0; cc < 2; cc++) {
                    int n = n0 + warp_n + nt * 8 + l4 * 2 + cc;
                    if (n < Nn)
                        Cw[(size_t)m * Nn + n] = acc[mt][nt][half * 2 + cc];
                }
            }
}

// ---------------- generic split-K reduction ----------------
__global__ void k_sreduce(const float* __restrict__ P, const float* __restrict__ bias,
                          const float* __restrict__ resid, float* __restrict__ C,
                          int Nn, int total, int nseg, int act) {
    int idx = blockIdx.x * 256 + threadIdx.x;
    if (idx >= total) return;
    float s = 0.f;
    for (int z = 0; z < nseg; z++) s += P[(size_t)z * total + idx];
    int n = idx % Nn;
    if (bias) s += bias[n];
    if (resid) s += resid[idx];
    if (act == 1) s = 0.5f * s * (1.0f + erff(s * 0.70710678118654752f));
    C[idx] = s;
}

// ---------------- fused: reduce + bias + resid -> x, AND rmsnorm -> xn ----------------
__global__ void k_sreduce_rms(const float* __restrict__ P, const float* __restrict__ bias,
                              const float* __restrict__ resid, float* __restrict__ x,
                              const float* __restrict__ w, float* __restrict__ xn,
                              int nseg) {
    int l = blockIdx.x, t = threadIdx.x;
    int idx = l * DM + t;
    const int total = LQ * DM;
    float s = 0.f;
    for (int z = 0; z < nseg; z++) s += P[(size_t)z * total + idx];
    s += bias[t];
    s += resid[idx];
    x[idx] = s;
    __shared__ float red[256];
    red[t] = s * s;
    __syncthreads();
    for (int st = 128; st > 0; st >>= 1) {
        if (t < st) red[t] += red[t + st];
        __syncthreads();
    }
    float r = rsqrtf(red[0] / (float)DM + 1e-6f);
    xn[idx] = s * r * w[t];
}

// ---------------- fused: qkv reduce + bias + RoPE -> qkv ----------------
__global__ void k_sreduce_rope(const float* __restrict__ P, const float* __restrict__ bias,
                               float* __restrict__ qkv, int nseg) {
    int l = blockIdx.x, t = threadIdx.x;   // t in [0,384)
    int d0 = 2 * t, d1 = d0 + 1;
    const int total = LQ * 768;
    int i0 = l * 768 + d0, i1 = i0 + 1;
    float s0 = 0.f, s1 = 0.f;
    for (int z = 0; z < nseg; z++) {
        s0 += P[(size_t)z * total + i0];
        s1 += P[(size_t)z * total + i1];
    }
    s0 += bias[d0];
    s1 += bias[d1];
    if (d0 < 2 * DM) {
        int dh = d0 & 63;
        int i = dh >> 1;
        float inv = (float)pow(10000.0, -(double)(2 * i) / (double)HDIM);
        float ang = (float)l * inv;
        float sn, cs;
        sincosf(ang, &sn, &cs);
        float o0 = s0 * cs - s1 * sn;
        float o1 = s0 * sn + s1 * cs;
        s0 = o0; s1 = o1;
    }
    qkv[i0] = s0;
    qkv[i1] = s1;
}

// ---------------- fused: ret reduce * need -> ret ----------------
__global__ void k_sreduce_need(const float* __restrict__ P, const float* __restrict__ need,
                               float* __restrict__ C, int nseg) {
    int idx = blockIdx.x * 256 + threadIdx.x;
    const int total = LQ * DM;
    if (idx >= total) return;
    float s = 0.f;
    for (int z = 0; z < nseg; z++) s += P[(size_t)z * total + idx];
    C[idx] = s * need[idx >> 8];
}

// ---------------- flash attention partials: chunk = 4 key tiles, 2 CTAs/SM ----
#define ASTR 72
#define ATTN_SMEM (4 * 64 * ASTR * 4)   // 73728 B
__global__ void __launch_bounds__(256, 2)
k_attn2(const float* __restrict__ qkv, float* __restrict__ pacc,
        float* __restrict__ pm, float* __restrict__ pl) {
    extern __shared__ float sf[];
    float* Qs = sf;
    float* Ks = sf + 64 * ASTR;
    float* Vs = sf + 2 * 64 * ASTR;
    float* Ps = sf + 3 * 64 * ASTR;

    int bx = blockIdx.x, h = blockIdx.y;
    int qb = 0, c = 0;
    {
        int accum = 0;
        for (int i = 0; i < 32; i++) {
            int nch = (i >> 2) + 1;
            if (bx < accum + nch) { qb = i; c = bx - accum; break; }
            accum += nch;
        }
    }
    const int q0 = qb * 64;
    const int tid = threadIdx.x;
    const int ty = tid >> 4, tx = tid & 15;
    const int lr = tid >> 2, lseg = (tid & 3) * 16;

    {
        const float4* src = (const float4*)(qkv + (size_t)(q0 + lr) * 768 + h * HDIM + lseg);
        float4* dst = (float4*)(Qs + lr * ASTR + lseg);
#pragma unroll
        for (int i = 0; i < 4; i++) dst[i] = src[i];
    }

    float m_[4], l_[4], acc[4][4];
#pragma unroll
    for (int i = 0; i < 4; i++) {
        m_[i] = -INFINITY; l_[i] = 0.f;
#pragma unroll
        for (int j = 0; j < 4; j++) acc[i][j] = 0.f;
    }

    int t0 = c * 4, t1 = min(c * 4 + 4, qb + 1);
    for (int t = t0; t < t1; t++) {
        int k0 = t * 64;
        {
            const float4* sk = (const float4*)(qkv + (size_t)(k0 + lr) * 768 + DM + h * HDIM + lseg);
            const float4* sv = (const float4*)(qkv + (size_t)(k0 + lr) * 768 + 2 * DM + h * HDIM + lseg);
            float4* dk = (float4*)(Ks + lr * ASTR + lseg);
            float4* dv = (float4*)(Vs + lr * ASTR + lseg);
#pragma unroll
            for (int i = 0; i < 4; i++) { dk[i] = sk[i]; dv[i] = sv[i]; }
        }
        __syncthreads();

        float s[4][4] = {};
#pragma unroll
        for (int d4 = 0; d4 < HDIM; d4 += 4) {
            float4 q4[4], k4[4];
#pragma unroll
            for (int i = 0; i < 4; i++) q4[i] = *(const float4*)(Qs + (ty * 4 + i) * ASTR + d4);
#pragma unroll
            for (int j = 0; j < 4; j++) k4[j] = *(const float4*)(Ks + (tx * 4 + j) * ASTR + d4);
#pragma unroll
            for (int i = 0; i < 4; i++)
#pragma unroll
                for (int j = 0; j < 4; j++)
                    s[i][j] += q4[i].x * k4[j].x + q4[i].y * k4[j].y +
                               q4[i].z * k4[j].z + q4[i].w * k4[j].w;
        }
#pragma unroll
        for (int i = 0; i < 4; i++)
#pragma unroll
            for (int j = 0; j < 4; j++) {
                s[i][j] *= 0.125f;
                if (k0 + tx * 4 + j > q0 + ty * 4 + i) s[i][j] = -INFINITY;
            }
#pragma unroll
        for (int i = 0; i < 4; i++) {
            float mt = fmaxf(fmaxf(s[i][0], s[i][1]), fmaxf(s[i][2], s[i][3]));
#pragma unroll
            for (int sh = 8; sh > 0; sh >>= 1) mt = fmaxf(mt, __shfl_xor_sync(0xffffffffu, mt, sh));
            float mn = fmaxf(m_[i], mt);
            float alpha = expf(m_[i] - mn);
            float p0 = expf(s[i][0] - mn), p1 = expf(s[i][1] - mn);
            float p2 = expf(s[i][2] - mn), p3 = expf(s[i][3] - mn);
            float rs = p0 + p1 + p2 + p3;
#pragma unroll
            for (int sh = 8; sh > 0; sh >>= 1) rs += __shfl_xor_sync(0xffffffffu, rs, sh);
            l_[i] = l_[i] * alpha + rs;
            m_[i] = mn;
#pragma unroll
            for (int j = 0; j < 4; j++) acc[i][j] *= alpha;
            *(float4*)(Ps + (ty * 4 + i) * ASTR + tx * 4) = make_float4(p0, p1, p2, p3);
        }
        __syncthreads();
#pragma unroll
        for (int k4i = 0; k4i < 64; k4i += 4) {
            float4 pv[4], v4[4];
#pragma unroll
            for (int i = 0; i < 4; i++) pv[i] = *(const float4*)(Ps + (ty * 4 + i) * ASTR + k4i);
#pragma unroll
            for (int kk = 0; kk < 4; kk++) v4[kk] = *(const float4*)(Vs + (k4i + kk) * ASTR + tx * 4);
#pragma unroll
            for (int i = 0; i < 4; i++) {
                acc[i][0] += pv[i].x * v4[0].x + pv[i].y * v4[1].x + pv[i].z * v4[2].x + pv[i].w * v4[3].x;
                acc[i][1] += pv[i].x * v4[0].y + pv[i].y * v4[1].y + pv[i].z * v4[2].y + pv[i].w * v4[3].y;
                acc[i][2] += pv[i].x * v4[0].z + pv[i].y * v4[1].z + pv[i].z * v4[2].z + pv[i].w * v4[3].z;
                acc[i][3] += pv[i].x * v4[0].w + pv[i].y * v4[1].w + pv[i].z * v4[2].w + pv[i].w * v4[3].w;
            }
        }
        __syncthreads();
    }

    int base = (h * NCHMAX + c) * LQ;
#pragma unroll
    for (int i = 0; i < 4; i++) {
        int q = q0 + ty * 4 + i;
        if (tx == 0) { pm[base + q] = m_[i]; pl[base + q] = l_[i]; }
        *(float4*)(pacc + ((size_t)(base + q)) * HDIM + tx * 4) =
            make_float4(acc[i][0], acc[i][1], acc[i][2], acc[i][3]);
    }
}

// ---------------- combine attention partials -> o ----------------
__global__ void k_attn_comb(const float* __restrict__ pacc, const float* __restrict__ pm,
                            const float* __restrict__ pl, float* __restrict__ o) {
    int q = blockIdx.x, h = blockIdx.y, d = threadIdx.x;
    int nch = ((q >> 6) >> 2) + 1;
    float M = -INFINITY;
    for (int c = 0; c < nch; c++) M = fmaxf(M, pm[(h * NCHMAX + c) * LQ + q]);
    float L = 0.f, A = 0.f;
    for (int c = 0; c < nch; c++) {
        float wgt = expf(pm[(h * NCHMAX + c) * LQ + q] - M);
        L += pl[(h * NCHMAX + c) * LQ + q] * wgt;
        A += pacc[((size_t)((h * NCHMAX + c) * LQ + q)) * HDIM + d] * wgt;
    }
    o[(size_t)q * DM + h * HDIM + d] = A / L;
}

// ---------------- row stats ----------------
__global__ void k_rowstats(const float* __restrict__ x,
                           const float* __restrict__ unc_w, const float* __restrict__ unc_b,
                           const float* __restrict__ sal_w, const float* __restrict__ sal_b,
                           const float* __restrict__ wg_w, const float* __restrict__ wg_b,
                           uint32_t* __restrict__ qnu, float* __restrict__ need,
                           float* __restrict__ sal, float* __restrict__ gate) {
    int l = blockIdx.x, t = threadIdx.x;
    __shared__ float r0[256], r1[256], r2[256], r3[256];
    float v = x[l * DM + t];
    r0[t] = v * v;
    r1[t] = v * unc_w[t];
    r2[t] = v * sal_w[t];
    r3[t] = v * wg_w[t];
    __syncthreads();
    for (int s = 128; s > 0; s >>= 1) {
        if (t < s) { r0[t] += r0[t + s]; r1[t] += r1[t + s]; r2[t] += r2[t + s]; r3[t] += r3[t + s]; }
        __syncthreads();
    }
    float norm = sqrtf(r0[0]);
    qnu[l * DM + t] = f2tf32(v / fmaxf(norm, 1e-12f));
    if (t == 0) {
        need[l] = 1.f / (1.f + expf(-(r1[0] + unc_b[0])));
        sal[l]  = 1.f / (1.f + expf(-(r2[0] + sal_b[0])));
        gate[l] = 1.f / (1.f + expf(-(r3[0] + wg_b[0])));
    }
}

// ---------------- normalize memory keys -> tf32 u32 ----------------
__global__ void k_knorm(const float* __restrict__ mk, uint32_t* __restrict__ knu) {
    int m = blockIdx.x, t = threadIdx.x;
    __shared__ float red[256];
    float v = mk[(size_t)m * DM + t];
    red[t] = v * v;
    __syncthreads();
    for (int s = 128; s > 0; s >>= 1) { if (t < s) red[t] += red[t + s]; __syncthreads(); }
    knu[(size_t)m * DM + t] = f2tf32(v / fmaxf(sqrtf(red[0]), 1e-12f));
}

// ---------------- memory softmax: normalize + in-place convert to tf32 u32 ----------------
__global__ void k_softmax_mem(float* __restrict__ res) {
    int l = blockIdx.x, t = threadIdx.x;
    __shared__ float red[256];
    float* row = res + (size_t)l * MMEM;
    uint32_t* rowu = (uint32_t*)row;
    float lm = -INFINITY;
    for (int m = t; m < MMEM; m += 256) lm = fmaxf(lm, row[m] * 5.0f);
    red[t] = lm; __syncthreads();
    for (int s = 128; s > 0; s >>= 1) { if (t < s) red[t] = fmaxf(red[t], red[t + s]); __syncthreads(); }
    float mx = red[0]; __syncthreads();
    float ls = 0.f;
    for (int m = t; m < MMEM; m += 256) { float p = expf(row[m] * 5.0f - mx); row[m] = p; ls += p; }
    red[t] = ls; __syncthreads();
    for (int s = 128; s > 0; s >>= 1) { if (t < s) red[t] += red[t + s]; __syncthreads(); }
    float inv = 1.f / red[0];
    __syncthreads();
    for (int m = t; m < MMEM; m += 256) rowu[m] = f2tf32(row[m] * inv);
}

// ---------------- gate penalty ----------------
__global__ void k_penalty(const float* __restrict__ sal, const float* __restrict__ gate,
                          float* __restrict__ out) {
    __shared__ float s[LQ];
    __shared__ float rn[256], rc[256];
    int t = threadIdx.x;
    for (int l = t; l < LQ; l += 256) s[l] = sal[l];
    __syncthreads();
    float num = 0.f, cnt = 0.f;
    for (int l = t; l < LQ; l += 256) {
        float v = s[l];
        int j0 = l - 15 < 0 ? 0 : l - 15;
        int j1 = l + 15 > LQ - 1 ? LQ - 1 : l + 15;
        float mx = -INFINITY;
        for (int j = j0; j <= j1; j++) mx = fmaxf(mx, s[j]);
        if (v == mx && v > 0.15f) {
            float g = gate[l];
            num += (1.f - g) * (1.f - g);
            cnt += 1.f;
        }
    }
    rn[t] = num; rc[t] = cnt;
    __syncthreads();
    for (int st = 128; st > 0; st >>= 1) {
        if (t < st) { rn[t] += rn[t + st]; rc[t] += rc[t + st]; }
        __syncthreads();
    }
    if (t == 0) out[0] = rc[0] > 0.f ? rn[0] / fmaxf(rc[0], 1.f) : 0.f;
}

// ---------------- host helpers ----------------
static void gemm_part(const float* A, const float* B, float* P,
                      int Mm, int Nn, int Kk, int nseg) {
    dim3 grid((Nn + 63) / 64, Mm / 64, nseg);
    k_gemm<<<grid, 128, GEMM_SMEM2>>>(A, B, P, Mm, Nn, Kk, Kk / nseg);
}
static void gemmp(const uint32_t* A, const uint32_t* B, float* C,
                  int Mm, int Nn, int Kk, int b_nt) {
    dim3 grid((Nn + 63) / 64, Mm / 64, 1);
    k_gemmp<<<grid, 128, GEMM_SMEM2>>>(A, B, C, Mm, Nn, Kk, b_nt, Kk);
}

extern "C" void kernel_launch(void* const* d_in, const int* in_sizes, int n_in,
                              void* d_out, int out_size) {
    const int*   tokens    = (const int*)d_in[0];
    const float* embed     = (const float*)d_in[1];
    const float* qkv_w     = (const float*)d_in[2];
    const float* qkv_b     = (const float*)d_in[3];
    const float* proj_w    = (const float*)d_in[4];
    const float* proj_b    = (const float*)d_in[5];
    const float* ln1_w     = (const float*)d_in[6];
    const float* mlp_w1    = (const float*)d_in[7];
    const float* mlp_b1    = (const float*)d_in[8];
    const float* mlp_w2    = (const float*)d_in[9];
    const float* mlp_b2    = (const float*)d_in[10];
    const float* ln2_w     = (const float*)d_in[11];
    const float* sal_w     = (const float*)d_in[12];
    const float* sal_b     = (const float*)d_in[13];
    const float* unc_w     = (const float*)d_in[14];
    const float* unc_b     = (const float*)d_in[15];
    const float* wg_w      = (const float*)d_in[16];
    const float* wg_b      = (const float*)d_in[17];
    const float* memproj_w = (const float*)d_in[18];
    const float* memproj_b = (const float*)d_in[19];
    const float* mem_k     = (const float*)d_in[20];
    const float* mem_v     = (const float*)d_in[21];
    float* out = (float*)d_out;

    cudaFuncSetAttribute(k_gemm, cudaFuncAttributeMaxDynamicSharedMemorySize, GEMM_SMEM2);
    cudaFuncSetAttribute(k_gemmp, cudaFuncAttributeMaxDynamicSharedMemorySize, GEMM_SMEM2);
    cudaFuncSetAttribute(k_attn2, cudaFuncAttributeMaxDynamicSharedMemorySize, ATTN_SMEM);

    float *x, *xn, *qkv, *o, *h1, *res, *ret, *xout, *split, *need, *sal, *gate;
    float *pacc, *pm, *pl;
    uint32_t *embu, *qnu, *knu, *mvu, *xoutu;
    cudaGetSymbolAddress((void**)&x, g_x);
    cudaGetSymbolAddress((void**)&xn, g_xn);
    cudaGetSymbolAddress((void**)&qkv, g_qkv);
    cudaGetSymbolAddress((void**)&o, g_o);
    cudaGetSymbolAddress((void**)&h1, g_h1);
    cudaGetSymbolAddress((void**)&res, g_res);
    cudaGetSymbolAddress((void**)&ret, g_ret);
    cudaGetSymbolAddress((void**)&xout, g_xout);
    cudaGetSymbolAddress((void**)&split, g_split);
    cudaGetSymbolAddress((void**)&need, g_need);
    cudaGetSymbolAddress((void**)&sal, g_sal);
    cudaGetSymbolAddress((void**)&gate, g_gate);
    cudaGetSymbolAddress((void**)&pacc, g_pacc);
    cudaGetSymbolAddress((void**)&pm, g_pm);
    cudaGetSymbolAddress((void**)&pl, g_pl);
    cudaGetSymbolAddress((void**)&embu, g_embu);
    cudaGetSymbolAddress((void**)&qnu, g_qnu);
    cudaGetSymbolAddress((void**)&knu, g_knu);
    cudaGetSymbolAddress((void**)&mvu, g_mvu);
    cudaGetSymbolAddress((void**)&xoutu, g_xoutu);

    // one-time conversions
    k_embed<<<(LQ * DM) / 256, 256>>>(tokens, embed, x);
    k_fcvt<<<(VOCAB * DM + 255) / 256, 256>>>(embed, embu, VOCAB * DM);
    k_fcvt<<<(MMEM * DM + 255) / 256, 256>>>(mem_v, mvu, MMEM * DM);
    k_knorm<<<MMEM, 256>>>(mem_k, knu);

    // initial rmsnorm for layer 0
    k_rmsnorm<<<LQ, 256>>>(x, ln1_w, xn);

    for (int li = 0; li < NLAYER; li++) {
        // qkv: partials (nseg=2) + fused reduce+bias+rope
        gemm_part(xn, qkv_w + (size_t)li * 3 * DM * DM, split, LQ, 3 * DM, DM, 2);
        k_sreduce_rope<<<LQ, 384>>>(split, qkv_b + li * 3 * DM, qkv, 2);
        {
            dim3 g(144, NH);
            k_attn2<<<g, 256, ATTN_SMEM>>>(qkv, pacc, pm, pl);
            dim3 gc(LQ, NH);
            k_attn_comb<<<gc, 64>>>(pacc, pm, pl, o);
        }
        // proj: partials (nseg=8) + fused reduce+resid -> x, rmsnorm(ln2) -> xn
        gemm_part(o, proj_w + (size_t)li * DM * DM, split, LQ, DM, DM, 8);
        k_sreduce_rms<<<LQ, 256>>>(split, proj_b + li * DM, x, x, ln2_w + li * DM, xn, 8);
        // mlp1: partials (nseg=2) + reduce+bias+gelu -> h1
        gemm_part(xn, mlp_w1 + (size_t)li * DFF * DM, split, LQ, DFF, DM, 2);
        k_sreduce<<<(LQ * DFF + 255) / 256, 256>>>(split, mlp_b1 + li * DFF, nullptr, h1,
                                                   DFF, LQ * DFF, 2, 1);
        // mlp2: partials (nseg=8) + fused reduce+resid -> x (+rms for next layer)
        gemm_part(h1, mlp_w2 + (size_t)li * DM * DFF, split, LQ, DM, DFF, 8);
        if (li < NLAYER - 1)
            k_sreduce_rms<<<LQ, 256>>>(split, mlp_b2 + li * DM, x, x,
                                       ln1_w + (li + 1) * DM, xn, 8);
        else
            k_sreduce<<<(LQ * DM + 255) / 256, 256>>>(split, mlp_b2 + li * DM, x, x,
                                                      DM, LQ * DM, 8, 0);
    }

    // landmark memory read (fast tier)
    k_rowstats<<<LQ, 256>>>(x, unc_w, unc_b, sal_w, sal_b, wg_w, wg_b,
                            qnu, need, sal, gate);
    gemmp(qnu, knu, res, LQ, MMEM, DM, 1);
    k_softmax_mem<<<LQ, 256>>>(res);
    {
        dim3 grid(DM / 64, LQ / 64, 8);
        k_gemmp<<<grid, 128, GEMM_SMEM2>>>((const uint32_t*)res, mvu, split,
                                           LQ, DM, MMEM, 0, MMEM / 8);
        k_sreduce_need<<<(LQ * DM + 255) / 256, 256>>>(split, need, ret, 8);
    }
    // memproj: accurate (partials + reduce w/ resid)
    gemm_part(ret, memproj_w, split, LQ, DM, DM, 8);
    k_sreduce<<<(LQ * DM + 255) / 256, 256>>>(split, memproj_b, x, xout, DM, LQ * DM, 8, 0);
    k_fcvt<<<(LQ * DM + 255) / 256, 256>>>(xout, xoutu, LQ * DM);

    // tied-head logits (fast tier)
    gemmp(xoutu, embu, out, LQ, VOCAB, DM, 1);

    if (out_size > LQ * VOCAB)
        k_penalty<<<1, 256>>>(sal, gate, out + (size_t)LQ * VOCAB);
}

// round 17
// speedup vs baseline: 1.0922x; 1.0922x over previous
#include <cuda_runtime.h>
#include <math.h>
#include <stdint.h>

#define LQ 2048
#define DM 256
#define NH 4
#define HDIM 64
#define NLAYER 6
#define MMEM 8192
#define VOCAB 50257
#define DFF 1024
#define NCHMAX 8

// ---------------- scratch ----------------
__device__ float g_x[LQ * DM];
__device__ float g_xn[LQ * DM];
__device__ float g_qkv[LQ * 3 * DM];
__device__ float g_o[LQ * DM];
__device__ float g_h1[LQ * DFF];
__device__ float g_res[(size_t)LQ * MMEM];   // scores; softmax converts in-place to tf32 u32
__device__ float g_ret[LQ * DM];
__device__ float g_split[4 * LQ * 768];      // split-K partials (24 MB)
__device__ float g_need[LQ];
__device__ float g_sal[LQ];
__device__ float g_gate[LQ];
__device__ float g_ropeinv[32];              // 10000^(-2i/64), double-pow exact
// fast-tier pre-converted tf32 (u32)
__device__ uint32_t g_embu[VOCAB * DM];
__device__ uint32_t g_qnu[LQ * DM];
__device__ uint32_t g_knu[MMEM * DM];
__device__ uint32_t g_mvu[MMEM * DM];
__device__ uint32_t g_xoutu[LQ * DM];
// flash-attention partials: [NH][NCHMAX][LQ][HDIM]
__device__ float g_pacc[NH * NCHMAX * LQ * HDIM];
__device__ float g_pm[NH * NCHMAX * LQ];
__device__ float g_pl[NH * NCHMAX * LQ];

__device__ __forceinline__ uint32_t f2tf32(float f) {
    uint32_t u;
    asm("cvt.rna.tf32.f32 %0, %1;" : "=r"(u) : "f"(f));
    return u;
}
__device__ __forceinline__ void tf32_split(float f, uint32_t& b, uint32_t& s) {
    b = f2tf32(f);
    s = f2tf32(f - __uint_as_float(b));
}
__device__ __forceinline__ void cp16(void* dst, const void* src, bool ok) {
    uint32_t sa = (uint32_t)__cvta_generic_to_shared(dst);
    int sz = ok ? 16 : 0;
    asm volatile("cp.async.ca.shared.global [%0], [%1], 16, %2;\n"
                 :: "r"(sa), "l"(src), "r"(sz));
}

#define MMA(c, A0, A1, A2, A3, B0, B1)                                        \
    asm volatile("mma.sync.aligned.m16n8k8.row.col.f32.tf32.tf32.f32 "        \
                 "{%0,%1,%2,%3}, {%4,%5,%6,%7}, {%8,%9}, {%0,%1,%2,%3};\n"    \
                 : "+f"(c[0]), "+f"(c[1]), "+f"(c[2]), "+f"(c[3])             \
                 : "r"(A0), "r"(A1), "r"(A2), "r"(A3), "r"(B0), "r"(B1))

// ---------------- rope inv table (exact double pow, computed once) ----------------
__global__ void k_ropetab(float* __restrict__ tab) {
    int i = threadIdx.x;   // 32 threads
    tab[i] = (float)pow(10000.0, -(double)(2 * i) / (double)HDIM);
}

// ---------------- elementwise float -> tf32 u32 ----------------
__global__ void k_fcvt(const float* __restrict__ in, uint32_t* __restrict__ ou, int n) {
    int i = blockIdx.x * 256 + threadIdx.x;
    if (i < n) ou[i] = f2tf32(in[i]);
}

// ---------------- embedding lookup ----------------
__global__ void k_embed(const int* __restrict__ tokens, const float* __restrict__ embed,
                        float* __restrict__ x) {
    int idx = blockIdx.x * 256 + threadIdx.x;
    int l = idx >> 8, d = idx & 255;
    x[idx] = embed[(size_t)tokens[l] * DM + d];
}

// ---------------- rmsnorm (standalone; once before the loop) ----------------
__global__ void k_rmsnorm(const float* __restrict__ x, const float* __restrict__ w,
                          float* __restrict__ xn) {
    int l = blockIdx.x, t = threadIdx.x;
    __shared__ float red[256];
    float v = x[l * DM + t];
    red[t] = v * v;
    __syncthreads();
    for (int s = 128; s > 0; s >>= 1) {
        if (t < s) red[t] += red[t + s];
        __syncthreads();
    }
    float r = rsqrtf(red[0] / (float)DM + 1e-6f);
    xn[l * DM + t] = v * r * w[t];
}

// ---------------- accurate tf32x3 GEMM: 64x64 CTA tile, 128 thr, 5 CTAs/SM ----
#define ASTR2 20
#define ATILE (64 * ASTR2)
#define STG2 (2 * ATILE)
#define GEMM_SMEM2 (2 * STG2 * 4)       // 20480 B
__global__ void __launch_bounds__(128, 5)
k_gemm(const float* __restrict__ A, const float* __restrict__ B,
       float* __restrict__ P, int Mm, int Nn, int Kk, int kseg) {
    extern __shared__ float smem[];
    const int n0 = blockIdx.x * 64, m0 = blockIdx.y * 64;
    const int tid = threadIdx.x;
    const int w = tid >> 5, lane = tid & 31;
    const int g = lane >> 2, l4 = lane & 3;
    const int warp_m = (w >> 1) * 32;
    const int warp_n = (w & 1) * 32;
    const int kbeg = blockIdx.z * kseg;
    const int kend = kbeg + kseg;

    float acc[2][4][4];
#pragma unroll
    for (int i = 0; i < 2; i++)
#pragma unroll
        for (int j = 0; j < 4; j++)
#pragma unroll
            for (int r = 0; r < 4; r++) acc[i][j][r] = 0.f;

    const int row = tid >> 1, col8 = (tid & 1) * 8;

    auto load_tiles = [&](int k0, int st) {
        float* As = smem + st * STG2;
        float* Bs = As + ATILE;
        const float* sa = A + (size_t)(m0 + row) * Kk + k0 + col8;
        float* da = As + row * ASTR2 + col8;
        cp16(da, sa, true);
        cp16(da + 4, sa + 4, true);
        const float* sb = B + (size_t)(n0 + row) * Kk + k0 + col8;
        float* db = Bs + row * ASTR2 + col8;
        cp16(db, sb, true);
        cp16(db + 4, sb + 4, true);
        asm volatile("cp.async.commit_group;\n");
    };

    load_tiles(kbeg, 0);
    int stage = 0;
    for (int k0 = kbeg; k0 < kend; k0 += 16) {
        bool more = (k0 + 16) < kend;
        if (more) {
            load_tiles(k0 + 16, stage ^ 1);
            asm volatile("cp.async.wait_group 1;\n");
        } else {
            asm volatile("cp.async.wait_group 0;\n");
        }
        __syncthreads();

        const float* Af = smem + stage * STG2;
        const float* Bf = Af + ATILE;
#pragma unroll
        for (int ks = 0; ks < 2; ks++) {
            const int kc = ks * 8;
            uint32_t ab[2][4], ax[2][4], bb[4][2], bx[4][2];
#pragma unroll
            for (int mt = 0; mt < 2; mt++) {
                int r = (warp_m + mt * 16 + g) * ASTR2 + kc + l4;
                tf32_split(Af[r],                 ab[mt][0], ax[mt][0]);
                tf32_split(Af[r + 8 * ASTR2],     ab[mt][1], ax[mt][1]);
                tf32_split(Af[r + 4],             ab[mt][2], ax[mt][2]);
                tf32_split(Af[r + 8 * ASTR2 + 4], ab[mt][3], ax[mt][3]);
            }
#pragma unroll
            for (int nt = 0; nt < 4; nt++) {
                int r = (warp_n + nt * 8 + g) * ASTR2 + kc + l4;
                tf32_split(Bf[r],     bb[nt][0], bx[nt][0]);
                tf32_split(Bf[r + 4], bb[nt][1], bx[nt][1]);
            }
#pragma unroll
            for (int mt = 0; mt < 2; mt++)
#pragma unroll
                for (int nt = 0; nt < 4; nt++)
                    MMA(acc[mt][nt], ab[mt][0], ab[mt][1], ab[mt][2], ab[mt][3],
                        bb[nt][0], bb[nt][1]);
#pragma unroll
            for (int mt = 0; mt < 2; mt++)
#pragma unroll
                for (int nt = 0; nt < 4; nt++)
                    MMA(acc[mt][nt], ab[mt][0], ab[mt][1], ab[mt][2], ab[mt][3],
                        bx[nt][0], bx[nt][1]);
#pragma unroll
            for (int mt = 0; mt < 2; mt++)
#pragma unroll
                for (int nt = 0; nt < 4; nt++)
                    MMA(acc[mt][nt], ax[mt][0], ax[mt][1], ax[mt][2], ax[mt][3],
                        bb[nt][0], bb[nt][1]);
        }
        __syncthreads();
        stage ^= 1;
    }

    float* Pw = P + (size_t)blockIdx.z * Mm * Nn;
#pragma unroll
    for (int mt = 0; mt < 2; mt++)
#pragma unroll
        for (int nt = 0; nt < 4; nt++)
#pragma unroll
            for (int half = 0; half < 2; half++) {
                int m = m0 + warp_m + mt * 16 + g + half * 8;
#pragma unroll
                for (int cc = 0; cc < 2; cc++) {
                    int n = n0 + warp_n + nt * 8 + l4 * 2 + cc;
                    if (n < Nn)
                        Pw[(size_t)m * Nn + n] = acc[mt][nt][half * 2 + cc];
                }
            }
}

// ---------------- fast 1x tf32 GEMM: 128x128 tile, 256 thr, 2 CTAs/SM (R15) ----
#define ASTRIDE 20
#define BSTRIDE 132
#define STG 2560
#define GEMM_SMEM (4 * STG * 4)
__global__ void __launch_bounds__(256, 2)
k_gemmp(const uint32_t* __restrict__ A, const uint32_t* __restrict__ B,
        float* __restrict__ C, int Mm, int Nn, int Kk, int b_nt, int kseg) {
    extern __shared__ uint32_t smu[];
    uint32_t* As = smu;
    uint32_t* Bs = smu + 2 * STG;

    const int n0 = blockIdx.x * 128, m0 = blockIdx.y * 128;
    const int tid = threadIdx.x;
    const int w = tid >> 5, lane = tid & 31;
    const int g = lane >> 2, l4 = lane & 3;
    const int warp_m = (w >> 2) * 64;
    const int warp_n = (w & 3) * 32;
    const int kbeg = blockIdx.z * kseg;
    const int kend = kbeg + kseg;

    float acc[4][4][4];
#pragma unroll
    for (int i = 0; i < 4; i++)
#pragma unroll
        for (int j = 0; j < 4; j++)
#pragma unroll
            for (int r = 0; r < 4; r++) acc[i][j][r] = 0.f;

    auto load_tiles = [&](int k0, int st) {
        {
            int row = tid >> 1, colb = (tid & 1) * 8;
            const uint32_t* src = A + (size_t)(m0 + row) * Kk + k0 + colb;
            uint32_t* dst = As + st * STG + row * ASTRIDE + colb;
            cp16(dst, src, true);
            cp16(dst + 4, src + 4, true);
        }
        if (b_nt) {
            int row = tid >> 1, colb = (tid & 1) * 8;
            int gn = n0 + row;
            bool ok = gn < Nn;
            const uint32_t* src = B + (size_t)(ok ? gn : 0) * Kk + k0 + colb;
            uint32_t* dst = Bs + st * STG + row * ASTRIDE + colb;
            cp16(dst, src, ok);
            cp16(dst + 4, src + 4, ok);
        } else {
            int k = tid >> 4, colb = (tid & 15) * 8;
            const uint32_t* src = B + (size_t)(k0 + k) * Nn + n0 + colb;
            uint32_t* dst = Bs + st * STG + k * BSTRIDE + colb;
            cp16(dst, src, true);
            cp16(dst + 4, src + 4, true);
        }
        asm volatile("cp.async.commit_group;\n");
    };

    load_tiles(kbeg, 0);
    int stage = 0;
    for (int k0 = kbeg; k0 < kend; k0 += 16) {
        bool more = (k0 + 16) < kend;
        if (more) {
            load_tiles(k0 + 16, stage ^ 1);
            asm volatile("cp.async.wait_group 1;\n");
        } else {
            asm volatile("cp.async.wait_group 0;\n");
        }
        __syncthreads();

        const uint32_t* Af = As + stage * STG;
        const uint32_t* Bf = Bs + stage * STG;
#pragma unroll
        for (int ks = 0; ks < 2; ks++) {
            const int kc = ks * 8;
            uint32_t ab[4][4], bb[4][2];
#pragma unroll
            for (int mt = 0; mt < 4; mt++) {
                int r = (warp_m + mt * 16 + g) * ASTRIDE + kc + l4;
                ab[mt][0] = Af[r];
                ab[mt][1] = Af[r + 8 * ASTRIDE];
                ab[mt][2] = Af[r + 4];
                ab[mt][3] = Af[r + 8 * ASTRIDE + 4];
            }
            if (b_nt) {
#pragma unroll
                for (int nt = 0; nt < 4; nt++) {
                    int r = (warp_n + nt * 8 + g) * ASTRIDE + kc + l4;
                    bb[nt][0] = Bf[r];
                    bb[nt][1] = Bf[r + 4];
                }
            } else {
#pragma unroll
                for (int nt = 0; nt < 4; nt++) {
                    int cn = warp_n + nt * 8 + g;
                    bb[nt][0] = Bf[(kc + l4) * BSTRIDE + cn];
                    bb[nt][1] = Bf[(kc + l4 + 4) * BSTRIDE + cn];
                }
            }
#pragma unroll
            for (int mt = 0; mt < 4; mt++)
#pragma unroll
                for (int nt = 0; nt < 4; nt++)
                    MMA(acc[mt][nt], ab[mt][0], ab[mt][1], ab[mt][2], ab[mt][3],
                        bb[nt][0], bb[nt][1]);
        }
        __syncthreads();
        stage ^= 1;
    }

    bool partial = (gridDim.z > 1);
    float* Cw = partial ? C + (size_t)blockIdx.z * Mm * Nn : C;
#pragma unroll
    for (int mt = 0; mt < 4; mt++)
#pragma unroll
        for (int nt = 0; nt < 4; nt++)
#pragma unroll
            for (int half = 0; half < 2; half++) {
                int m = m0 + warp_m + mt * 16 + g + half * 8;
#pragma unroll
                for (int cc = 0; cc < 2; cc++) {
                    int n = n0 + warp_n + nt * 8 + l4 * 2 + cc;
                    if (n < Nn)
                        Cw[(size_t)m * Nn + n] = acc[mt][nt][half * 2 + cc];
                }
            }
}

// ---------------- generic split-K reduction ----------------
__global__ void k_sreduce(const float* __restrict__ P, const float* __restrict__ bias,
                          const float* __restrict__ resid, float* __restrict__ C,
                          int Nn, int total, int nseg, int act) {
    int idx = blockIdx.x * 256 + threadIdx.x;
    if (idx >= total) return;
    float s = 0.f;
    for (int z = 0; z < nseg; z++) s += P[(size_t)z * total + idx];
    int n = idx % Nn;
    if (bias) s += bias[n];
    if (resid) s += resid[idx];
    if (act == 1) s = 0.5f * s * (1.0f + erff(s * 0.70710678118654752f));
    C[idx] = s;
}

// ---------------- fused: memproj reduce + bias + resid -> tf32 u32 ----------------
__global__ void k_sreduce_cvt(const float* __restrict__ P, const float* __restrict__ bias,
                              const float* __restrict__ resid, uint32_t* __restrict__ Cu,
                              int nseg) {
    int idx = blockIdx.x * 256 + threadIdx.x;
    const int total = LQ * DM;
    if (idx >= total) return;
    float s = 0.f;
    for (int z = 0; z < nseg; z++) s += P[(size_t)z * total + idx];
    s += bias[idx & 255];
    s += resid[idx];
    Cu[idx] = f2tf32(s);
}

// ---------------- fused: reduce + bias + resid -> x, AND rmsnorm -> xn ----------------
__global__ void k_sreduce_rms(const float* __restrict__ P, const float* __restrict__ bias,
                              const float* __restrict__ resid, float* __restrict__ x,
                              const float* __restrict__ w, float* __restrict__ xn,
                              int nseg) {
    int l = blockIdx.x, t = threadIdx.x;
    int idx = l * DM + t;
    const int total = LQ * DM;
    float s = 0.f;
    for (int z = 0; z < nseg; z++) s += P[(size_t)z * total + idx];
    s += bias[t];
    s += resid[idx];
    x[idx] = s;
    __shared__ float red[256];
    red[t] = s * s;
    __syncthreads();
    for (int st = 128; st > 0; st >>= 1) {
        if (t < st) red[t] += red[t + st];
        __syncthreads();
    }
    float r = rsqrtf(red[0] / (float)DM + 1e-6f);
    xn[idx] = s * r * w[t];
}

// ---------------- fused: qkv reduce + bias + RoPE -> qkv (table-driven) ----------------
__global__ void k_sreduce_rope(const float* __restrict__ P, const float* __restrict__ bias,
                               const float* __restrict__ ropeinv,
                               float* __restrict__ qkv, int nseg) {
    int l = blockIdx.x, t = threadIdx.x;   // t in [0,384)
    int d0 = 2 * t, d1 = d0 + 1;
    const int total = LQ * 768;
    int i0 = l * 768 + d0, i1 = i0 + 1;
    float s0 = 0.f, s1 = 0.f;
    for (int z = 0; z < nseg; z++) {
        s0 += P[(size_t)z * total + i0];
        s1 += P[(size_t)z * total + i1];
    }
    s0 += bias[d0];
    s1 += bias[d1];
    if (d0 < 2 * DM) {
        int i = (d0 & 63) >> 1;
        float inv = ropeinv[i];
        float ang = (float)l * inv;
        float sn, cs;
        sincosf(ang, &sn, &cs);
        float o0 = s0 * cs - s1 * sn;
        float o1 = s0 * sn + s1 * cs;
        s0 = o0; s1 = o1;
    }
    qkv[i0] = s0;
    qkv[i1] = s1;
}

// ---------------- fused: ret reduce * need -> ret ----------------
__global__ void k_sreduce_need(const float* __restrict__ P, const float* __restrict__ need,
                               float* __restrict__ C, int nseg) {
    int idx = blockIdx.x * 256 + threadIdx.x;
    const int total = LQ * DM;
    if (idx >= total) return;
    float s = 0.f;
    for (int z = 0; z < nseg; z++) s += P[(size_t)z * total + idx];
    C[idx] = s * need[idx >> 8];
}

// ---------------- flash attention partials: chunk = 4 key tiles, 2 CTAs/SM ----
#define ASTR 72
#define ATTN_SMEM (4 * 64 * ASTR * 4)
__global__ void __launch_bounds__(256, 2)
k_attn2(const float* __restrict__ qkv, float* __restrict__ pacc,
        float* __restrict__ pm, float* __restrict__ pl) {
    extern __shared__ float sf[];
    float* Qs = sf;
    float* Ks = sf + 64 * ASTR;
    float* Vs = sf + 2 * 64 * ASTR;
    float* Ps = sf + 3 * 64 * ASTR;

    int bx = blockIdx.x, h = blockIdx.y;
    int qb = 0, c = 0;
    {
        int accum = 0;
        for (int i = 0; i < 32; i++) {
            int nch = (i >> 2) + 1;
            if (bx < accum + nch) { qb = i; c = bx - accum; break; }
            accum += nch;
        }
    }
    const int q0 = qb * 64;
    const int tid = threadIdx.x;
    const int ty = tid >> 4, tx = tid & 15;
    const int lr = tid >> 2, lseg = (tid & 3) * 16;

    {
        const float4* src = (const float4*)(qkv + (size_t)(q0 + lr) * 768 + h * HDIM + lseg);
        float4* dst = (float4*)(Qs + lr * ASTR + lseg);
#pragma unroll
        for (int i = 0; i < 4; i++) dst[i] = src[i];
    }

    float m_[4], l_[4], acc[4][4];
#pragma unroll
    for (int i = 0; i < 4; i++) {
        m_[i] = -INFINITY; l_[i] = 0.f;
#pragma unroll
        for (int j = 0; j < 4; j++) acc[i][j] = 0.f;
    }

    int t0 = c * 4, t1 = min(c * 4 + 4, qb + 1);
    for (int t = t0; t < t1; t++) {
        int k0 = t * 64;
        {
            const float4* sk = (const float4*)(qkv + (size_t)(k0 + lr) * 768 + DM + h * HDIM + lseg);
            const float4* sv = (const float4*)(qkv + (size_t)(k0 + lr) * 768 + 2 * DM + h * HDIM + lseg);
            float4* dk = (float4*)(Ks + lr * ASTR + lseg);
            float4* dv = (float4*)(Vs + lr * ASTR + lseg);
#pragma unroll
            for (int i = 0; i < 4; i++) { dk[i] = sk[i]; dv[i] = sv[i]; }
        }
        __syncthreads();

        float s[4][4] = {};
#pragma unroll
        for (int d4 = 0; d4 < HDIM; d4 += 4) {
            float4 q4[4], k4[4];
#pragma unroll
            for (int i = 0; i < 4; i++) q4[i] = *(const float4*)(Qs + (ty * 4 + i) * ASTR + d4);
#pragma unroll
            for (int j = 0; j < 4; j++) k4[j] = *(const float4*)(Ks + (tx * 4 + j) * ASTR + d4);
#pragma unroll
            for (int i = 0; i < 4; i++)
#pragma unroll
                for (int j = 0; j < 4; j++)
                    s[i][j] += q4[i].x * k4[j].x + q4[i].y * k4[j].y +
                               q4[i].z * k4[j].z + q4[i].w * k4[j].w;
        }
#pragma unroll
        for (int i = 0; i < 4; i++)
#pragma unroll
            for (int j = 0; j < 4; j++) {
                s[i][j] *= 0.125f;
                if (k0 + tx * 4 + j > q0 + ty * 4 + i) s[i][j] = -INFINITY;
            }
#pragma unroll
        for (int i = 0; i < 4; i++) {
            float mt = fmaxf(fmaxf(s[i][0], s[i][1]), fmaxf(s[i][2], s[i][3]));
#pragma unroll
            for (int sh = 8; sh > 0; sh >>= 1) mt = fmaxf(mt, __shfl_xor_sync(0xffffffffu, mt, sh));
            float mn = fmaxf(m_[i], mt);
            float alpha = expf(m_[i] - mn);
            float p0 = expf(s[i][0] - mn), p1 = expf(s[i][1] - mn);
            float p2 = expf(s[i][2] - mn), p3 = expf(s[i][3] - mn);
            float rs = p0 + p1 + p2 + p3;
#pragma unroll
            for (int sh = 8; sh > 0; sh >>= 1) rs += __shfl_xor_sync(0xffffffffu, rs, sh);
            l_[i] = l_[i] * alpha + rs;
            m_[i] = mn;
#pragma unroll
            for (int j = 0; j < 4; j++) acc[i][j] *= alpha;
            *(float4*)(Ps + (ty * 4 + i) * ASTR + tx * 4) = make_float4(p0, p1, p2, p3);
        }
        __syncthreads();
#pragma unroll
        for (int k4i = 0; k4i < 64; k4i += 4) {
            float4 pv[4], v4[4];
#pragma unroll
            for (int i = 0; i < 4; i++) pv[i] = *(const float4*)(Ps + (ty * 4 + i) * ASTR + k4i);
#pragma unroll
            for (int kk = 0; kk < 4; kk++) v4[kk] = *(const float4*)(Vs + (k4i + kk) * ASTR + tx * 4);
#pragma unroll
            for (int i = 0; i < 4; i++) {
                acc[i][0] += pv[i].x * v4[0].x + pv[i].y * v4[1].x + pv[i].z * v4[2].x + pv[i].w * v4[3].x;
                acc[i][1] += pv[i].x * v4[0].y + pv[i].y * v4[1].y + pv[i].z * v4[2].y + pv[i].w * v4[3].y;
                acc[i][2] += pv[i].x * v4[0].z + pv[i].y * v4[1].z + pv[i].z * v4[2].z + pv[i].w * v4[3].z;
                acc[i][3] += pv[i].x * v4[0].w + pv[i].y * v4[1].w + pv[i].z * v4[2].w + pv[i].w * v4[3].w;
            }
        }
        __syncthreads();
    }

    int base = (h * NCHMAX + c) * LQ;
#pragma unroll
    for (int i = 0; i < 4; i++) {
        int q = q0 + ty * 4 + i;
        if (tx == 0) { pm[base + q] = m_[i]; pl[base + q] = l_[i]; }
        *(float4*)(pacc + ((size_t)(base + q)) * HDIM + tx * 4) =
            make_float4(acc[i][0], acc[i][1], acc[i][2], acc[i][3]);
    }
}

// ---------------- combine attention partials -> o ----------------
__global__ void k_attn_comb(const float* __restrict__ pacc, const float* __restrict__ pm,
                            const float* __restrict__ pl, float* __restrict__ o) {
    int q = blockIdx.x, h = blockIdx.y, d = threadIdx.x;
    int nch = ((q >> 6) >> 2) + 1;
    float M = -INFINITY;
    for (int c = 0; c < nch; c++) M = fmaxf(M, pm[(h * NCHMAX + c) * LQ + q]);
    float L = 0.f, A = 0.f;
    for (int c = 0; c < nch; c++) {
        float wgt = expf(pm[(h * NCHMAX + c) * LQ + q] - M);
        L += pl[(h * NCHMAX + c) * LQ + q] * wgt;
        A += pacc[((size_t)((h * NCHMAX + c) * LQ + q)) * HDIM + d] * wgt;
    }
    o[(size_t)q * DM + h * HDIM + d] = A / L;
}

// ---------------- row stats ----------------
__global__ void k_rowstats(const float* __restrict__ x,
                           const float* __restrict__ unc_w, const float* __restrict__ unc_b,
                           const float* __restrict__ sal_w, const float* __restrict__ sal_b,
                           const float* __restrict__ wg_w, const float* __restrict__ wg_b,
                           uint32_t* __restrict__ qnu, float* __restrict__ need,
                           float* __restrict__ sal, float* __restrict__ gate) {
    int l = blockIdx.x, t = threadIdx.x;
    __shared__ float r0[256], r1[256], r2[256], r3[256];
    float v = x[l * DM + t];
    r0[t] = v * v;
    r1[t] = v * unc_w[t];
    r2[t] = v * sal_w[t];
    r3[t] = v * wg_w[t];
    __syncthreads();
    for (int s = 128; s > 0; s >>= 1) {
        if (t < s) { r0[t] += r0[t + s]; r1[t] += r1[t + s]; r2[t] += r2[t + s]; r3[t] += r3[t + s]; }
        __syncthreads();
    }
    float norm = sqrtf(r0[0]);
    qnu[l * DM + t] = f2tf32(v / fmaxf(norm, 1e-12f));
    if (t == 0) {
        need[l] = 1.f / (1.f + expf(-(r1[0] + unc_b[0])));
        sal[l]  = 1.f / (1.f + expf(-(r2[0] + sal_b[0])));
        gate[l] = 1.f / (1.f + expf(-(r3[0] + wg_b[0])));
    }
}

// ---------------- normalize memory keys -> tf32 u32 ----------------
__global__ void k_knorm(const float* __restrict__ mk, uint32_t* __restrict__ knu) {
    int m = blockIdx.x, t = threadIdx.x;
    __shared__ float red[256];
    float v = mk[(size_t)m * DM + t];
    red[t] = v * v;
    __syncthreads();
    for (int s = 128; s > 0; s >>= 1) { if (t < s) red[t] += red[t + s]; __syncthreads(); }
    knu[(size_t)m * DM + t] = f2tf32(v / fmaxf(sqrtf(red[0]), 1e-12f));
}

// ---------------- memory softmax: normalize + in-place convert to tf32 u32 ----------------
__global__ void k_softmax_mem(float* __restrict__ res) {
    int l = blockIdx.x, t = threadIdx.x;
    __shared__ float red[256];
    float* row = res + (size_t)l * MMEM;
    uint32_t* rowu = (uint32_t*)row;
    float lm = -INFINITY;
    for (int m = t; m < MMEM; m += 256) lm = fmaxf(lm, row[m] * 5.0f);
    red[t] = lm; __syncthreads();
    for (int s = 128; s > 0; s >>= 1) { if (t < s) red[t] = fmaxf(red[t], red[t + s]); __syncthreads(); }
    float mx = red[0]; __syncthreads();
    float ls = 0.f;
    for (int m = t; m < MMEM; m += 256) { float p = expf(row[m] * 5.0f - mx); row[m] = p; ls += p; }
    red[t] = ls; __syncthreads();
    for (int s = 128; s > 0; s >>= 1) { if (t < s) red[t] += red[t + s]; __syncthreads(); }
    float inv = 1.f / red[0];
    __syncthreads();
    for (int m = t; m < MMEM; m += 256) rowu[m] = f2tf32(row[m] * inv);
}

// ---------------- gate penalty ----------------
__global__ void k_penalty(const float* __restrict__ sal, const float* __restrict__ gate,
                          float* __restrict__ out) {
    __shared__ float s[LQ];
    __shared__ float rn[256], rc[256];
    int t = threadIdx.x;
    for (int l = t; l < LQ; l += 256) s[l] = sal[l];
    __syncthreads();
    float num = 0.f, cnt = 0.f;
    for (int l = t; l < LQ; l += 256) {
        float v = s[l];
        int j0 = l - 15 < 0 ? 0 : l - 15;
        int j1 = l + 15 > LQ - 1 ? LQ - 1 : l + 15;
        float mx = -INFINITY;
        for (int j = j0; j <= j1; j++) mx = fmaxf(mx, s[j]);
        if (v == mx && v > 0.15f) {
            float g = gate[l];
            num += (1.f - g) * (1.f - g);
            cnt += 1.f;
        }
    }
    rn[t] = num; rc[t] = cnt;
    __syncthreads();
    for (int st = 128; st > 0; st >>= 1) {
        if (t < st) { rn[t] += rn[t + st]; rc[t] += rc[t + st]; }
        __syncthreads();
    }
    if (t == 0) out[0] = rc[0] > 0.f ? rn[0] / fmaxf(rc[0], 1.f) : 0.f;
}

// ---------------- host helpers ----------------
static void gemm_part(const float* A, const float* B, float* P,
                      int Mm, int Nn, int Kk, int nseg) {
    dim3 grid((Nn + 63) / 64, Mm / 64, nseg);
    k_gemm<<<grid, 128, GEMM_SMEM2>>>(A, B, P, Mm, Nn, Kk, Kk / nseg);
}
static void gemmp(const uint32_t* A, const uint32_t* B, float* C,
                  int Mm, int Nn, int Kk, int b_nt) {
    dim3 grid((Nn + 127) / 128, Mm / 128, 1);
    k_gemmp<<<grid, 256, GEMM_SMEM>>>(A, B, C, Mm, Nn, Kk, b_nt, Kk);
}

extern "C" void kernel_launch(void* const* d_in, const int* in_sizes, int n_in,
                              void* d_out, int out_size) {
    const int*   tokens    = (const int*)d_in[0];
    const float* embed     = (const float*)d_in[1];
    const float* qkv_w     = (const float*)d_in[2];
    const float* qkv_b     = (const float*)d_in[3];
    const float* proj_w    = (const float*)d_in[4];
    const float* proj_b    = (const float*)d_in[5];
    const float* ln1_w     = (const float*)d_in[6];
    const float* mlp_w1    = (const float*)d_in[7];
    const float* mlp_b1    = (const float*)d_in[8];
    const float* mlp_w2    = (const float*)d_in[9];
    const float* mlp_b2    = (const float*)d_in[10];
    const float* ln2_w     = (const float*)d_in[11];
    const float* sal_w     = (const float*)d_in[12];
    const float* sal_b     = (const float*)d_in[13];
    const float* unc_w     = (const float*)d_in[14];
    const float* unc_b     = (const float*)d_in[15];
    const float* wg_w      = (const float*)d_in[16];
    const float* wg_b      = (const float*)d_in[17];
    const float* memproj_w = (const float*)d_in[18];
    const float* memproj_b = (const float*)d_in[19];
    const float* mem_k     = (const float*)d_in[20];
    const float* mem_v     = (const float*)d_in[21];
    float* out = (float*)d_out;

    cudaFuncSetAttribute(k_gemm, cudaFuncAttributeMaxDynamicSharedMemorySize, GEMM_SMEM2);
    cudaFuncSetAttribute(k_gemmp, cudaFuncAttributeMaxDynamicSharedMemorySize, GEMM_SMEM);
    cudaFuncSetAttribute(k_attn2, cudaFuncAttributeMaxDynamicSharedMemorySize, ATTN_SMEM);

    float *x, *xn, *qkv, *o, *h1, *res, *ret, *split, *need, *sal, *gate;
    float *pacc, *pm, *pl, *ropeinv;
    uint32_t *embu, *qnu, *knu, *mvu, *xoutu;
    cudaGetSymbolAddress((void**)&x, g_x);
    cudaGetSymbolAddress((void**)&xn, g_xn);
    cudaGetSymbolAddress((void**)&qkv, g_qkv);
    cudaGetSymbolAddress((void**)&o, g_o);
    cudaGetSymbolAddress((void**)&h1, g_h1);
    cudaGetSymbolAddress((void**)&res, g_res);
    cudaGetSymbolAddress((void**)&ret, g_ret);
    cudaGetSymbolAddress((void**)&split, g_split);
    cudaGetSymbolAddress((void**)&need, g_need);
    cudaGetSymbolAddress((void**)&sal, g_sal);
    cudaGetSymbolAddress((void**)&gate, g_gate);
    cudaGetSymbolAddress((void**)&pacc, g_pacc);
    cudaGetSymbolAddress((void**)&pm, g_pm);
    cudaGetSymbolAddress((void**)&pl, g_pl);
    cudaGetSymbolAddress((void**)&ropeinv, g_ropeinv);
    cudaGetSymbolAddress((void**)&embu, g_embu);
    cudaGetSymbolAddress((void**)&qnu, g_qnu);
    cudaGetSymbolAddress((void**)&knu, g_knu);
    cudaGetSymbolAddress((void**)&mvu, g_mvu);
    cudaGetSymbolAddress((void**)&xoutu, g_xoutu);

    // one-time conversions
    k_ropetab<<<1, 32>>>(ropeinv);
    k_embed<<<(LQ * DM) / 256, 256>>>(tokens, embed, x);
    k_fcvt<<<(VOCAB * DM + 255) / 256, 256>>>(embed, embu, VOCAB * DM);
    k_fcvt<<<(MMEM * DM + 255) / 256, 256>>>(mem_v, mvu, MMEM * DM);
    k_knorm<<<MMEM, 256>>>(mem_k, knu);

    // initial rmsnorm for layer 0
    k_rmsnorm<<<LQ, 256>>>(x, ln1_w, xn);

    for (int li = 0; li < NLAYER; li++) {
        // qkv: partials (nseg=2) + fused reduce+bias+rope
        gemm_part(xn, qkv_w + (size_t)li * 3 * DM * DM, split, LQ, 3 * DM, DM, 2);
        k_sreduce_rope<<<LQ, 384>>>(split, qkv_b + li * 3 * DM, ropeinv, qkv, 2);
        {
            dim3 g(144, NH);
            k_attn2<<<g, 256, ATTN_SMEM>>>(qkv, pacc, pm, pl);
            dim3 gc(LQ, NH);
            k_attn_comb<<<gc, 64>>>(pacc, pm, pl, o);
        }
        // proj: partials (nseg=8) + fused reduce+resid -> x, rmsnorm(ln2) -> xn
        gemm_part(o, proj_w + (size_t)li * DM * DM, split, LQ, DM, DM, 8);
        k_sreduce_rms<<<LQ, 256>>>(split, proj_b + li * DM, x, x, ln2_w + li * DM, xn, 8);
        // mlp1: partials (nseg=2) + reduce+bias+gelu -> h1
        gemm_part(xn, mlp_w1 + (size_t)li * DFF * DM, split, LQ, DFF, DM, 2);
        k_sreduce<<<(LQ * DFF + 255) / 256, 256>>>(split, mlp_b1 + li * DFF, nullptr, h1,
                                                   DFF, LQ * DFF, 2, 1);
        // mlp2: partials (nseg=8) + fused reduce+resid -> x (+rms for next layer)
        gemm_part(h1, mlp_w2 + (size_t)li * DM * DFF, split, LQ, DM, DFF, 8);
        if (li < NLAYER - 1)
            k_sreduce_rms<<<LQ, 256>>>(split, mlp_b2 + li * DM, x, x,
                                       ln1_w + (li + 1) * DM, xn, 8);
        else
            k_sreduce<<<(LQ * DM + 255) / 256, 256>>>(split, mlp_b2 + li * DM, x, x,
                                                      DM, LQ * DM, 8, 0);
    }

    // landmark memory read (fast tier)
    k_rowstats<<<LQ, 256>>>(x, unc_w, unc_b, sal_w, sal_b, wg_w, wg_b,
                            qnu, need, sal, gate);
    gemmp(qnu, knu, res, LQ, MMEM, DM, 1);
    k_softmax_mem<<<LQ, 256>>>(res);
    {
        dim3 grid(2, LQ / 128, 8);
        k_gemmp<<<grid, 256, GEMM_SMEM>>>((const uint32_t*)res, mvu, split,
                                          LQ, DM, MMEM, 0, MMEM / 8);
        k_sreduce_need<<<(LQ * DM + 255) / 256, 256>>>(split, need, ret, 8);
    }
    // memproj: accurate partials + fused reduce+resid -> tf32 u32 (xoutu)
    gemm_part(ret, memproj_w, split, LQ, DM, DM, 8);
    k_sreduce_cvt<<<(LQ * DM + 255) / 256, 256>>>(split, memproj_b, x, xoutu, 8);

    // tied-head logits (fast tier)
    gemmp(xoutu, embu, out, LQ, VOCAB, DM, 1);

    if (out_size > LQ * VOCAB)
        k_penalty<<<1, 256>>>(sal, gate, out + (size_t)LQ * VOCAB);
}